// round 7
// baseline (speedup 1.0000x reference)
#include <cuda_runtime.h>
#include <math.h>

// Problem constants
#define PN   4096
#define TT   128
#define AA   32
#define KEL  409          // int(4096 * 0.1)
#define INFF 1e30f

// ---------------- scratch (no allocations allowed) ----------------
__device__ float g_dists[PN];
__device__ int   g_eidx[KEL];
__device__ float g_edist[KEL];
__device__ float g_w[KEL];
__device__ float g_scalars[2];   // [0] = ssum, [1] = 1/(ssum+1e-9)

// =====================================================================
// Kernel A: DTW min-plus DP, one warp per problem p.
// Row recurrence new[j] = min(min(prev[j+1],prev[j]), new[j-1]) + c[j]
// solved per-row as: s = prefix_sum(c); new[j] = s[j] + prefmin(m[k]-s[k-1])
// Each lane owns 4 consecutive columns (j = 4*lane+q).
// =====================================================================
__global__ void __launch_bounds__(256) dtw_kernel(const float* __restrict__ obs) {
    const unsigned FULL = 0xffffffffu;
    int warpId = (blockIdx.x * blockDim.x + threadIdx.x) >> 5;
    int lane   = threadIdx.x & 31;
    if (warpId >= PN) return;

    const float4* cbase = (const float4*)(obs + (size_t)warpId * TT * TT);

    // prevnew[j] = D_prev_row[j+1]; init row0: D[0][1..128] = INF
    float v0 = INFF, v1 = INFF, v2 = INFF, v3 = INFF;
    float carry = 0.0f;      // D_prev_row[0]: 0 for first row, INF after

    float4 c = cbase[lane];  // prefetch row 0

    #pragma unroll 1
    for (int i = 0; i < TT; i++) {
        float4 cn;
        if (i + 1 < TT) cn = cbase[(i + 1) * 32 + lane];

        // shifted[j] = prevnew[j-1]  (cross-lane for q==0)
        float up  = __shfl_up_sync(FULL, v3, 1);
        float sh0 = (lane == 0) ? carry : up;

        float m0 = fminf(v0, sh0);
        float m1 = fminf(v1, v0);
        float m2 = fminf(v2, v1);
        float m3 = fminf(v3, v2);

        // local inclusive prefix sums of c
        float s0 = c.x;
        float s1 = s0 + c.y;
        float s2 = s1 + c.z;
        float s3 = s2 + c.w;

        // warp inclusive +scan of lane aggregates
        float sum = s3;
        #pragma unroll
        for (int off = 1; off < 32; off <<= 1) {
            float t = __shfl_up_sync(FULL, sum, off);
            if (lane >= off) sum += t;
        }
        float base = sum - s3;      // exclusive prefix for this lane
        s0 += base; s1 += base; s2 += base; s3 += base;

        // t[j] = m[j] - s_exclusive[j]
        float t0 = m0 - base;
        float t1 = m1 - s0;
        float t2 = m2 - s1;
        float t3 = m3 - s2;

        // local inclusive prefix min
        float p0 = t0;
        float p1 = fminf(p0, t1);
        float p2 = fminf(p1, t2);
        float p3 = fminf(p2, t3);

        // warp inclusive min-scan of lane aggregates
        float mn = p3;
        #pragma unroll
        for (int off = 1; off < 32; off <<= 1) {
            float t = __shfl_up_sync(FULL, mn, off);
            if (lane >= off) mn = fminf(mn, t);
        }
        float ex = __shfl_up_sync(FULL, mn, 1);   // exclusive (preceding lanes)
        if (lane == 0) ex = INFF;

        v0 = s0 + fminf(p0, ex);
        v1 = s1 + fminf(p1, ex);
        v2 = s2 + fminf(p2, ex);
        v3 = s3 + fminf(p3, ex);

        carry = INFF;
        c = cn;
    }

    if (lane == 31) g_dists[warpId] = v3;   // D[T][T]
}

// =====================================================================
// Kernel B: exact top-K selection via rank counting.
// rank(p) = #{ j : d_j < d_p  or (d_j == d_p and j < p) }  (total order)
// rank is a permutation => element with rank < K writes slot 'rank'
// directly. This reproduces top_k's sorted-ascending, tie-by-index order.
// =====================================================================
__global__ void __launch_bounds__(256) rank_kernel() {
    __shared__ float sd[PN];
    for (int i = threadIdx.x; i < PN; i += blockDim.x) sd[i] = g_dists[i];
    __syncthreads();

    int warp = threadIdx.x >> 5;
    int lane = threadIdx.x & 31;

    #pragma unroll
    for (int e = 0; e < 4; e++) {
        int p = blockIdx.x * 32 + warp * 4 + e;
        float d = sd[p];
        int cnt = 0;
        #pragma unroll 4
        for (int j = lane; j < PN; j += 32) {
            float dj = sd[j];
            cnt += (dj < d) || (dj == d && j < p);
        }
        #pragma unroll
        for (int off = 16; off; off >>= 1)
            cnt += __shfl_down_sync(0xffffffffu, cnt, off);
        if (lane == 0 && cnt < KEL) {
            g_eidx[cnt]  = p;
            g_edist[cnt] = d;
        }
    }
}

// =====================================================================
// Kernel C: softmax-style elite scores. One block, 512 threads.
// =====================================================================
__global__ void __launch_bounds__(512) score_kernel() {
    __shared__ float sred[512];
    int tid = threadIdx.x;

    float d = (tid < KEL) ? g_edist[tid] : INFF;

    // min reduce
    sred[tid] = d; __syncthreads();
    #pragma unroll
    for (int s = 256; s; s >>= 1) {
        if (tid < s) sred[tid] = fminf(sred[tid], sred[tid + s]);
        __syncthreads();
    }
    float mind = sred[0]; __syncthreads();

    float e = (tid < KEL) ? expf(0.5f * (mind - d)) : 0.0f;

    // sum reduce of e
    sred[tid] = e; __syncthreads();
    #pragma unroll
    for (int s = 256; s; s >>= 1) {
        if (tid < s) sred[tid] += sred[tid + s];
        __syncthreads();
    }
    float E = sred[0]; __syncthreads();

    float wk = e / E;
    if (tid < KEL) g_w[tid] = wk;

    // ssum = sum of normalized scores (matches reference recompute)
    sred[tid] = (tid < KEL) ? wk : 0.0f; __syncthreads();
    #pragma unroll
    for (int s = 256; s; s >>= 1) {
        if (tid < s) sred[tid] += sred[tid + s];
        __syncthreads();
    }
    if (tid == 0) {
        float ssum = sred[0];
        g_scalars[0] = ssum;
        g_scalars[1] = 1.0f / (ssum + 1e-9f);
    }
}

// =====================================================================
// Kernel D: elite-gathered weighted mean/std per (t, a). One block per t.
// Only elite rows of noise are read (6.7 MB instead of 64 MB).
// =====================================================================
__global__ void __launch_bounds__(256) stats_kernel(
    const float* __restrict__ noise,   // [T, P, A]
    const float* __restrict__ means,   // [T, 1, A]
    const float* __restrict__ stds,    // [T, 1, A]
    float* __restrict__ out)           // [2, T, 1, A]
{
    int t    = blockIdx.x;
    int lane = threadIdx.x & 31;       // a index
    int warp = threadIdx.x >> 5;       // 8 warps

    __shared__ float sw[KEL];
    __shared__ int   si[KEL];
    __shared__ float red1[8][32];
    __shared__ float red2[8][32];

    for (int i = threadIdx.x; i < KEL; i += blockDim.x) {
        sw[i] = g_w[i];
        si[i] = g_eidx[i];
    }
    __syncthreads();

    float mean_ta = means[t * AA + lane];
    float std_ta  = stds [t * AA + lane];
    const float* nbase = noise + (size_t)t * PN * AA;

    float S1 = 0.0f, S2 = 0.0f;
    for (int k = warp; k < KEL; k += 8) {
        float wk = sw[k];
        int   p  = si[k];
        float x  = mean_ta + std_ta * nbase[p * AA + lane];  // coalesced 128B
        x = fminf(fmaxf(x, -1.0f), 1.0f);
        S1 += wk * x;
        S2 += wk * x * x;
    }
    red1[warp][lane] = S1;
    red2[warp][lane] = S2;
    __syncthreads();

    if (warp == 0) {
        float s1 = 0.0f, s2 = 0.0f;
        #pragma unroll
        for (int i = 0; i < 8; i++) { s1 += red1[i][lane]; s2 += red2[i][lane]; }

        float W     = g_scalars[0];
        float recip = g_scalars[1];
        float mu  = s1 * recip;
        float var = fmaxf((s2 - 2.0f * mu * s1 + mu * mu * W) * recip, 0.0f);
        float sd  = fminf(fmaxf(sqrtf(var), 0.05f), 1.0f);

        out[t * AA + lane]            = 0.1f * mean_ta + 0.9f * mu;  // means_new
        out[TT * AA + t * AA + lane]  = sd;                          // _std
    }
}

// =====================================================================
extern "C" void kernel_launch(void* const* d_in, const int* in_sizes, int n_in,
                              void* d_out, int out_size) {
    const float* obs   = (const float*)d_in[0];  // [P, T, T]
    const float* means = (const float*)d_in[1];  // [T, 1, A]
    const float* stds  = (const float*)d_in[2];  // [T, 1, A]
    const float* noise = (const float*)d_in[3];  // [T, P, A]
    float* out = (float*)d_out;                  // [2, T, 1, A]

    dtw_kernel  <<<PN / 8, 256>>>(obs);          // 4096 warps, 1 per problem
    rank_kernel <<<PN / 32, 256>>>();            // 128 blocks x 32 elements
    score_kernel<<<1, 512>>>();
    stats_kernel<<<TT, 256>>>(noise, means, stds, out);
}

// round 8
// speedup vs baseline: 1.2859x; 1.2859x over previous
#include <cuda_runtime.h>
#include <math.h>

// Problem constants
#define PN   4096
#define TT   128
#define AA   32
#define KEL  409          // int(4096 * 0.1)
#define INFF 1e30f

// ---------------- scratch (no allocations allowed) ----------------
__device__ float g_dists[PN];
__device__ int   g_eidx[KEL];
__device__ float g_edist[KEL];
__device__ float g_w[KEL];
__device__ float g_scalars[2];   // [0] = ssum, [1] = 1/(ssum+1e-9)

// =====================================================================
// Kernel A: DTW min-plus DP, one warp per problem p.
// Row recurrence new[j] = min(min(prev[j+1],prev[j]), new[j-1]) + c[j]
// solved per-row as: s = prefix_sum(c); new[j] = s[j] + prefmin(m[k]-s[k-1])
// Each lane owns 4 consecutive columns (j = 4*lane+q).
//
// Software-pipelined: the +scan for row i+1 (depends only on c) is computed
// during row i's min-scan, with the two 5-step SHFL chains interleaved so
// their 26-cycle RAW latencies overlap. Loads prefetched 2 rows ahead.
// =====================================================================
__global__ void __launch_bounds__(256) dtw_kernel(const float* __restrict__ obs) {
    const unsigned FULL = 0xffffffffu;
    int warpId = (blockIdx.x * blockDim.x + threadIdx.x) >> 5;
    int lane   = threadIdx.x & 31;
    if (warpId >= PN) return;

    const float4* cbase = (const float4*)(obs + (size_t)warpId * TT * TT);

    // prevnew[j] = D_prev_row[j+1]; init row0: D[0][1..128] = INF
    float v0 = INFF, v1 = INFF, v2 = INFF, v3 = INFF;
    float carry = 0.0f;      // D_prev_row[0]: 0 for first row, INF after

    // ---- prologue: sums for row 0 ----
    float4 c0 = cbase[lane];
    float s0 = c0.x;
    float s1 = s0 + c0.y;
    float s2 = s1 + c0.z;
    float s3 = s2 + c0.w;
    {
        float sum = s3;
        #pragma unroll
        for (int off = 1; off < 32; off <<= 1) {
            float t = __shfl_up_sync(FULL, sum, off);
            if (lane >= off) sum += t;
        }
        float base0 = sum - s3;
        s0 += base0; s1 += base0; s2 += base0; s3 += base0;
        c0.x = base0;            // stash exclusive base in c0.x's register slot
    }
    float base = c0.x;

    float4 cn = cbase[32 + lane];   // row 1 costs

    #pragma unroll 2
    for (int i = 0; i < TT; i++) {
        // prefetch row i+2 (clamped, unconditional -> keeps MLP up)
        int nl = (i + 2 < TT) ? (i + 2) : (TT - 1);
        float4 cf = cbase[nl * 32 + lane];

        // --- next-row local sums (independent of v chain) ---
        float ns0 = cn.x;
        float ns1 = ns0 + cn.y;
        float ns2 = ns1 + cn.z;
        float ns3 = ns2 + cn.w;

        // --- current-row min chain setup (depends on previous row's v) ---
        float up  = __shfl_up_sync(FULL, v3, 1);
        float sh0 = (lane == 0) ? carry : up;

        float m0 = fminf(v0, sh0);
        float m1 = fminf(v1, v0);
        float m2 = fminf(v2, v1);
        float m3 = fminf(v3, v2);

        float t0 = m0 - base;
        float t1 = m1 - s0;
        float t2 = m2 - s1;
        float t3 = m3 - s2;

        float p0 = t0;
        float p1 = fminf(p0, t1);
        float p2 = fminf(p1, t2);
        float p3 = fminf(p2, t3);

        // --- interleaved warp scans: +scan(next sums) and min-scan(current) ---
        float nsum = ns3;
        float mn   = p3;
        #pragma unroll
        for (int off = 1; off < 32; off <<= 1) {
            float ta = __shfl_up_sync(FULL, nsum, off);
            float tb = __shfl_up_sync(FULL, mn, off);
            if (lane >= off) {
                nsum += ta;
                mn    = fminf(mn, tb);
            }
        }

        float ex = __shfl_up_sync(FULL, mn, 1);   // exclusive min (preceding lanes)
        if (lane == 0) ex = INFF;

        float nbase = nsum - ns3;                  // exclusive +prefix for next row

        v0 = s0 + fminf(p0, ex);
        v1 = s1 + fminf(p1, ex);
        v2 = s2 + fminf(p2, ex);
        v3 = s3 + fminf(p3, ex);

        // rotate pipeline state
        base = nbase;
        s0 = ns0 + nbase;
        s1 = ns1 + nbase;
        s2 = ns2 + nbase;
        s3 = ns3 + nbase;
        carry = INFF;
        cn = cf;
    }

    if (lane == 31) g_dists[warpId] = v3;   // D[T][T]
}

// =====================================================================
// Kernel B: exact top-K selection via rank counting.
// rank(p) = #{ j : d_j < d_p  or (d_j == d_p and j < p) }  (total order)
// rank is a permutation => element with rank < K writes slot 'rank'
// directly. This reproduces top_k's sorted-ascending, tie-by-index order.
// =====================================================================
__global__ void __launch_bounds__(256) rank_kernel() {
    __shared__ float sd[PN];
    for (int i = threadIdx.x; i < PN; i += blockDim.x) sd[i] = g_dists[i];
    __syncthreads();

    int warp = threadIdx.x >> 5;
    int lane = threadIdx.x & 31;

    #pragma unroll
    for (int e = 0; e < 4; e++) {
        int p = blockIdx.x * 32 + warp * 4 + e;
        float d = sd[p];
        int cnt = 0;
        #pragma unroll 4
        for (int j = lane; j < PN; j += 32) {
            float dj = sd[j];
            cnt += (dj < d) || (dj == d && j < p);
        }
        #pragma unroll
        for (int off = 16; off; off >>= 1)
            cnt += __shfl_down_sync(0xffffffffu, cnt, off);
        if (lane == 0 && cnt < KEL) {
            g_eidx[cnt]  = p;
            g_edist[cnt] = d;
        }
    }
}

// =====================================================================
// Kernel C: softmax-style elite scores. One block, 512 threads.
// =====================================================================
__global__ void __launch_bounds__(512) score_kernel() {
    __shared__ float sred[512];
    int tid = threadIdx.x;

    float d = (tid < KEL) ? g_edist[tid] : INFF;

    // min reduce
    sred[tid] = d; __syncthreads();
    #pragma unroll
    for (int s = 256; s; s >>= 1) {
        if (tid < s) sred[tid] = fminf(sred[tid], sred[tid + s]);
        __syncthreads();
    }
    float mind = sred[0]; __syncthreads();

    float e = (tid < KEL) ? expf(0.5f * (mind - d)) : 0.0f;

    // sum reduce of e
    sred[tid] = e; __syncthreads();
    #pragma unroll
    for (int s = 256; s; s >>= 1) {
        if (tid < s) sred[tid] += sred[tid + s];
        __syncthreads();
    }
    float E = sred[0]; __syncthreads();

    float wk = e / E;
    if (tid < KEL) g_w[tid] = wk;

    // ssum = sum of normalized scores (matches reference recompute)
    sred[tid] = (tid < KEL) ? wk : 0.0f; __syncthreads();
    #pragma unroll
    for (int s = 256; s; s >>= 1) {
        if (tid < s) sred[tid] += sred[tid + s];
        __syncthreads();
    }
    if (tid == 0) {
        float ssum = sred[0];
        g_scalars[0] = ssum;
        g_scalars[1] = 1.0f / (ssum + 1e-9f);
    }
}

// =====================================================================
// Kernel D: elite-gathered weighted mean/std per (t, a). One block per t,
// 1024 threads (32 warps) for 4x the gather MLP vs the 256-thread version.
// Only elite rows of noise are read (6.7 MB instead of 64 MB).
// =====================================================================
__global__ void __launch_bounds__(1024) stats_kernel(
    const float* __restrict__ noise,   // [T, P, A]
    const float* __restrict__ means,   // [T, 1, A]
    const float* __restrict__ stds,    // [T, 1, A]
    float* __restrict__ out)           // [2, T, 1, A]
{
    int t    = blockIdx.x;
    int lane = threadIdx.x & 31;       // a index
    int warp = threadIdx.x >> 5;       // 0..31

    __shared__ float sw[KEL];
    __shared__ int   si[KEL];
    __shared__ float red1[32][32];
    __shared__ float red2[32][32];

    for (int i = threadIdx.x; i < KEL; i += blockDim.x) {
        sw[i] = g_w[i];
        si[i] = g_eidx[i];
    }
    __syncthreads();

    float mean_ta = means[t * AA + lane];
    float std_ta  = stds [t * AA + lane];
    const float* nbase = noise + (size_t)t * PN * AA;

    float S1 = 0.0f, S2 = 0.0f;
    #pragma unroll 4
    for (int k = warp; k < KEL; k += 32) {
        float wk = sw[k];
        int   p  = si[k];
        float x  = mean_ta + std_ta * __ldg(nbase + p * AA + lane); // coalesced 128B
        x = fminf(fmaxf(x, -1.0f), 1.0f);
        S1 += wk * x;
        S2 += wk * x * x;
    }
    red1[warp][lane] = S1;
    red2[warp][lane] = S2;
    __syncthreads();

    if (warp == 0) {
        float s1 = 0.0f, s2 = 0.0f;
        #pragma unroll
        for (int i = 0; i < 32; i++) { s1 += red1[i][lane]; s2 += red2[i][lane]; }

        float W     = g_scalars[0];
        float recip = g_scalars[1];
        float mu  = s1 * recip;
        float var = fmaxf((s2 - 2.0f * mu * s1 + mu * mu * W) * recip, 0.0f);
        float sd  = fminf(fmaxf(sqrtf(var), 0.05f), 1.0f);

        out[t * AA + lane]            = 0.1f * mean_ta + 0.9f * mu;  // means_new
        out[TT * AA + t * AA + lane]  = sd;                          // _std
    }
}

// =====================================================================
extern "C" void kernel_launch(void* const* d_in, const int* in_sizes, int n_in,
                              void* d_out, int out_size) {
    const float* obs   = (const float*)d_in[0];  // [P, T, T]
    const float* means = (const float*)d_in[1];  // [T, 1, A]
    const float* stds  = (const float*)d_in[2];  // [T, 1, A]
    const float* noise = (const float*)d_in[3];  // [T, P, A]
    float* out = (float*)d_out;                  // [2, T, 1, A]

    dtw_kernel  <<<PN / 8, 256>>>(obs);          // 4096 warps, 1 per problem
    rank_kernel <<<PN / 32, 256>>>();            // 128 blocks x 32 elements
    score_kernel<<<1, 512>>>();
    stats_kernel<<<TT, 1024>>>(noise, means, stds, out);
}